// round 17
// baseline (speedup 1.0000x reference)
#include <cuda_runtime.h>
#include <cuda_fp16.h>
#include <cstdint>
#include <math.h>

#define NN 100000
#define EE 1600000
#define ET 1700000      // edges + self loops
#define H 14
#define C 7
#define HC 98
#define CP 8            // padded channels (slot 7 carries alsrc fp16)
#define HCP 112         // H * CP
#define FIN 256
#define BN 128          // GEMM1 N: 112 packed xh + 14 aldst + 2 unused
#define CAP 64          // bucket capacity per node (P(deg>63) ~ 1e-16)

#define TSTRIDE 12      // smem row stride in b32 (48B; conflict-free for ldmatrix)
#define BUFB32 (128 * TSTRIDE)      // b32 per buffer
#define BUFBYTES (BUFB32 * 4)       // 6144 bytes

// ---------------- scratch (device globals; reused across both layers) ----------
__device__ __align__(16) __half g_xh[NN * HCP];  // layer-1 [N,H,8] fp16; ch7=alsrc
__device__ __align__(16) __half g_xh2[NN * HCP]; // layer-2 (k_node<0> out)
__device__ float g_aldst[NN * H];    // layer-1 dst logits
__device__ float g_aldst2[NN * H];   // layer-2 dst logits
__device__ int g_cnt[NN];            // in-degree (filled by scatter)
__device__ __align__(16) int g_bucket[NN * CAP]; // per-destination source lists
__device__ __align__(16) __half g_Bext[BN * FIN]; // extended B, n-major fp16

__device__ __forceinline__ float lrelu(float v) {
    return v > 0.0f ? v : 0.2f * v;
}

__device__ __forceinline__ unsigned int f2h2(float a, float b) {
    const __half2 h = __floats2half2_rn(a, b);
    return *(const unsigned int*)&h;
}

__device__ __forceinline__ void mma_f16(float* c, const unsigned int* a,
                                        unsigned int b0, unsigned int b1) {
    asm volatile(
        "mma.sync.aligned.m16n8k16.row.col.f32.f16.f16.f32 "
        "{%0,%1,%2,%3},{%4,%5,%6,%7},{%8,%9},{%0,%1,%2,%3};"
        : "+f"(c[0]), "+f"(c[1]), "+f"(c[2]), "+f"(c[3])
        : "r"(a[0]), "r"(a[1]), "r"(a[2]), "r"(a[3]), "r"(b0), "r"(b1));
}

__device__ __forceinline__ void ldsm_x4(unsigned int& r0, unsigned int& r1,
                                        unsigned int& r2, unsigned int& r3,
                                        unsigned int addr) {
    asm volatile(
        "ldmatrix.sync.aligned.m8n8.x4.shared.b16 {%0,%1,%2,%3}, [%4];"
        : "=r"(r0), "=r"(r1), "=r"(r2), "=r"(r3) : "r"(addr));
}

__device__ __forceinline__ void cp_async16(unsigned int dst, const void* src) {
    asm volatile("cp.async.cg.shared.global [%0], [%1], 16;" :: "r"(dst), "l"(src));
}

// ---------------- bucket CSR build ---------------------------------------------
__global__ void k_zero() {
    const int i = blockIdx.x * blockDim.x + threadIdx.x;
    if (i < NN) g_cnt[i] = 0;
}

__global__ void k_scatter(const int* __restrict__ ei) {
    const int e = blockIdx.x * blockDim.x + threadIdx.x;
    if (e >= ET) return;
    int s, d;
    if (e < EE) { s = ei[e]; d = ei[EE + e]; } else { s = d = e - EE; }
    const int pos = atomicAdd(&g_cnt[d], 1);
    g_bucket[(d << 6) + pos] = s;
}

// ---------------- build extended B (fp16, n-major): xh + alsrc + aldst cols ----
__global__ void k_prep(const float* __restrict__ W1,
                       const float* __restrict__ a_src,
                       const float* __restrict__ a_dst) {
    const int i = blockIdx.x * blockDim.x + threadIdx.x;  // k*BN + col
    if (i >= FIN * BN) return;
    const int k = i / BN, col = i % BN;
    float v = 0.0f;
    if (col < HCP) {
        const int h = col >> 3, c = col & 7;
        if (c < C) {
            v = W1[k * HC + h * C + c];
        } else {  // alsrc column for head h
            float s = 0.0f;
#pragma unroll
            for (int cc = 0; cc < C; cc++)
                s = fmaf(W1[k * HC + h * C + cc], a_src[h * C + cc], s);
            v = s;
        }
    } else if (col < HCP + H) {  // aldst column for head col-112
        const int h = col - HCP;
        float s = 0.0f;
#pragma unroll
        for (int cc = 0; cc < C; cc++)
            s = fmaf(W1[k * HC + h * C + cc], a_dst[h * C + cc], s);
        v = s;
    }
    g_Bext[col * FIN + k] = __float2half_rn(v);   // n-major (transposed)
}

// ---------------- GEMM1 (FP16 MMA + ldmatrix + cp.async B) ---------------------
// cols 0..111 -> g_xh fp16 packed (alsrc in ch7); cols 112..125 -> g_aldst fp32
__global__ __launch_bounds__(256) void k_gemm1(const float* __restrict__ x) {
    __shared__ unsigned int As32[2][BUFB32];  // fp16x2, 12 b32/row
    __shared__ unsigned int Bs32[2][BUFB32];  // fp16x2, 12 b32/row (n-major)
    const int tid = threadIdx.x;
    const int warp = tid >> 5, lane = tid & 31;
    const int gid = lane >> 2, t4 = lane & 3;
    const int wm = warp >> 1, wn = warp & 1;
    const int bm = blockIdx.x * 128;
    const int rb0 = wm * 32;
    const int cb  = wn * 64;

    // A cooperative load: 2 float4 per thread (128 rows x 16 k)
    const int idx0 = tid * 2, idx1 = tid * 2 + 1;
    const int arow0 = idx0 >> 2, akq0 = idx0 & 3;
    const int arow1 = idx1 >> 2, akq1 = idx1 & 3;
    const bool aok0 = (bm + arow0 < NN);
    const bool aok1 = (bm + arow1 < NN);

    // B cp.async addressing: thread -> (col, 16B half)
    const unsigned int b_base = (unsigned int)__cvta_generic_to_shared(&Bs32[0][0]);
    const unsigned int b_dst = (tid >> 1) * 48 + (tid & 1) * 16;   // bytes in buffer
    const char* b_src = (const char*)g_Bext + (tid >> 1) * 512 + (tid & 1) * 16;

    // ldmatrix lane addresses (bytes, relative to buffer 0)
    const unsigned int a_base = (unsigned int)__cvta_generic_to_shared(&As32[0][0]);
    const unsigned int a_addr0 = a_base + (rb0 + (lane & 15)) * 48 + (lane >> 4) * 16;
    const unsigned int a_addr1 = a_addr0 + 16 * 48;
    unsigned int b_addr[4];
#pragma unroll
    for (int p = 0; p < 4; p++)
        b_addr[p] = b_base + (cb + p * 16 + ((lane >> 4) & 1) * 8 + (lane & 7)) * 48
                  + ((lane >> 3) & 1) * 16;

    float acc[2][8][4];
#pragma unroll
    for (int mt = 0; mt < 2; mt++)
#pragma unroll
        for (int nt = 0; nt < 8; nt++)
#pragma unroll
            for (int q = 0; q < 4; q++) acc[mt][nt][q] = 0.0f;

    const float4 Z4 = make_float4(0.f, 0.f, 0.f, 0.f);
    float4 pa0, pa1;

    // prologue: tile 0 (A via registers, B via cp.async)
    cp_async16(b_base + b_dst, b_src);
    asm volatile("cp.async.commit_group;");
    pa0 = aok0 ? *(const float4*)&x[(size_t)(bm + arow0) * FIN + akq0 * 4] : Z4;
    pa1 = aok1 ? *(const float4*)&x[(size_t)(bm + arow1) * FIN + akq1 * 4] : Z4;
    As32[0][arow0 * TSTRIDE + akq0 * 2 + 0] = f2h2(pa0.x, pa0.y);
    As32[0][arow0 * TSTRIDE + akq0 * 2 + 1] = f2h2(pa0.z, pa0.w);
    As32[0][arow1 * TSTRIDE + akq1 * 2 + 0] = f2h2(pa1.x, pa1.y);
    As32[0][arow1 * TSTRIDE + akq1 * 2 + 1] = f2h2(pa1.z, pa1.w);
    asm volatile("cp.async.wait_group 0;");
    __syncthreads();

#pragma unroll 1
    for (int t = 0; t < 16; t++) {
        const unsigned int boff = (t & 1) ? BUFBYTES : 0;
        const unsigned int nboff = boff ^ BUFBYTES;
        // prefetch next tile: A into registers, B via cp.async (overlaps MMA)
        if (t < 15) {
            const int k0 = (t + 1) * 16;
            cp_async16(b_base + nboff + b_dst, b_src + (t + 1) * 32);
            asm volatile("cp.async.commit_group;");
            pa0 = aok0 ? *(const float4*)&x[(size_t)(bm + arow0) * FIN + k0 + akq0 * 4] : Z4;
            pa1 = aok1 ? *(const float4*)&x[(size_t)(bm + arow1) * FIN + k0 + akq1 * 4] : Z4;
        }
        // one k16 MMA step on current buffer: 2 A-LDSM + 4 B-LDSM + 16 MMA
        {
            unsigned int a[2][4], bf[4][4];
            ldsm_x4(a[0][0], a[0][1], a[0][2], a[0][3], a_addr0 + boff);
            ldsm_x4(a[1][0], a[1][1], a[1][2], a[1][3], a_addr1 + boff);
#pragma unroll
            for (int p = 0; p < 4; p++)
                ldsm_x4(bf[p][0], bf[p][1], bf[p][2], bf[p][3], b_addr[p] + boff);
#pragma unroll
            for (int nt = 0; nt < 8; nt++) {
                const unsigned int b0 = bf[nt >> 1][(nt & 1) * 2 + 0];
                const unsigned int b1 = bf[nt >> 1][(nt & 1) * 2 + 1];
#pragma unroll
                for (int mt = 0; mt < 2; mt++) mma_f16(acc[mt][nt], a[mt], b0, b1);
            }
        }
        // store prefetched A into the other buffer; wait for B copy; sync
        if (t < 15) {
            const int nb = (t & 1) ^ 1;
            As32[nb][arow0 * TSTRIDE + akq0 * 2 + 0] = f2h2(pa0.x, pa0.y);
            As32[nb][arow0 * TSTRIDE + akq0 * 2 + 1] = f2h2(pa0.z, pa0.w);
            As32[nb][arow1 * TSTRIDE + akq1 * 2 + 0] = f2h2(pa1.x, pa1.y);
            As32[nb][arow1 * TSTRIDE + akq1 * 2 + 1] = f2h2(pa1.z, pa1.w);
        }
        asm volatile("cp.async.wait_group 0;");
        __syncthreads();
    }

    // epilogue: packed fp16 store (cols<112) or fp32 aldst store (cols 112..125)
#pragma unroll
    for (int mt = 0; mt < 2; mt++) {
        const int r0 = bm + rb0 + mt * 16 + gid;
        const int r1 = r0 + 8;
#pragma unroll
        for (int nt = 0; nt < 8; nt++) {
            const int col = cb + nt * 8 + t4 * 2;
            if (col < HCP) {
                if (r0 < NN)
                    *(__half2*)&g_xh[(size_t)r0 * HCP + col] =
                        __floats2half2_rn(acc[mt][nt][0], acc[mt][nt][1]);
                if (r1 < NN)
                    *(__half2*)&g_xh[(size_t)r1 * HCP + col] =
                        __floats2half2_rn(acc[mt][nt][2], acc[mt][nt][3]);
            } else {
                const int h0 = col - HCP, h1 = h0 + 1;
                if (r0 < NN) {
                    if (h0 < H) g_aldst[r0 * H + h0] = acc[mt][nt][0];
                    if (h1 < H) g_aldst[r0 * H + h1] = acc[mt][nt][1];
                }
                if (r1 < NN) {
                    if (h0 < H) g_aldst[r1 * H + h0] = acc[mt][nt][2];
                    if (h1 < H) g_aldst[r1 * H + h1] = acc[mt][nt][3];
                }
            }
        }
    }
}

// ---------------- fused node pass ------------------------------------------------
// MODE 0: reads g_xh/g_aldst; epilogue computes layer-2 projection + logits
//         (fused gemm2al) into g_xh2/g_aldst2.
// MODE 1: reads g_xh2/g_aldst2; writes final log_softmax to out.
template<int MODE>
__global__ __launch_bounds__(448, 3) void k_node(const float* __restrict__ b,
                                                 const float* __restrict__ W2,
                                                 const float* __restrict__ a_src2,
                                                 const float* __restrict__ a_dst2,
                                                 float* __restrict__ out) {
    __shared__ float sm[32][H][CP];          // 14 KB
    __shared__ float hsm[32][C];             // layer-1 node outputs (MODE 0)
    __shared__ float W2s[C][HC];
    __shared__ float As2[HC], Ad2[HC];
    const int tid = threadIdx.x;             // 448 = 32 nodes * 14 heads
    const int ln = tid / H;
    const int h  = tid % H;
    const int n  = blockIdx.x * 32 + ln;

    if (MODE == 0) {
        for (int i = tid; i < C * HC; i += 448) W2s[i / HC][i % HC] = W2[i];
        for (int i = tid; i < HC; i += 448) { As2[i] = a_src2[i]; Ad2[i] = a_dst2[i]; }
    }

    const __half* xin = (MODE == 0) ? g_xh : g_xh2;
    const float* alin = (MODE == 0) ? g_aldst : g_aldst2;

    if (n < NN) {
        const int cnt = g_cnt[n];
        const int base = n << 6;
        const float ad = alin[n * H + h];
        float den = 0.0f;
        const __half2 NEG2 = __float2half2_rn(-INFINITY);
        __half2 ah0 = NEG2, ah1 = NEG2, ah2 = NEG2, ah3 = NEG2;

        for (int j0 = 0; j0 < cnt; j0 += 4) {
            const int4 q = *(const int4*)&g_bucket[base + j0];
            const int m = cnt - j0;
            int ss[4] = {q.x, q.y, q.z, q.w};
            uint4 u[4];
#pragma unroll
            for (int k = 0; k < 4; k++)
                if (k < m) u[k] = *(const uint4*)&xin[(size_t)ss[k] * HCP + h * CP];
#pragma unroll
            for (int k = 0; k < 4; k++) {
                if (k < m) {
                    const __half2* hp = (const __half2*)&u[k];
                    const float als = __half2float(__high2half(hp[3]));
                    const float l = lrelu(als + ad);
                    const float w = __expf(l);
                    den += w;
                    const __half2 w2 = __float2half2_rn(w);
                    ah0 = __hmax2(ah0, __hmul2(w2, hp[0]));
                    ah1 = __hmax2(ah1, __hmul2(w2, hp[1]));
                    ah2 = __hmax2(ah2, __hmul2(w2, hp[2]));
                    ah3 = __hmax2(ah3, __hmul2(w2, hp[3]));  // .y garbage, discarded
                }
            }
        }
        const float inv = 1.0f / den;        // den > 0 (self loop => deg >= 1)
        const float2 F0 = __half22float2(ah0);
        const float2 F1 = __half22float2(ah1);
        const float2 F2 = __half22float2(ah2);
        const float2 F3 = __half22float2(ah3);
        sm[ln][h][0] = F0.x * inv;
        sm[ln][h][1] = F0.y * inv;
        sm[ln][h][2] = F1.x * inv;
        sm[ln][h][3] = F1.y * inv;
        sm[ln][h][4] = F2.x * inv;
        sm[ln][h][5] = F2.y * inv;
        sm[ln][h][6] = F3.x * inv;
    }
    __syncthreads();

    if (MODE == 0) {
        // head-mean + bias + relu -> hsm
        if (tid < 32 * C) {
            const int l2 = tid / C, c = tid % C;
            float s = 0.0f;
#pragma unroll
            for (int hh = 0; hh < H; hh++) s += sm[l2][hh][c];
            hsm[l2][c] = fmaxf(s * (1.0f / H) + b[c], 0.0f);
        }
        __syncthreads();
        // fused layer-2 projection + logits: thread (ln, h)
        if (n < NN) {
            float hv[C];
#pragma unroll
            for (int k = 0; k < C; k++) hv[k] = hsm[ln][k];
            float o[C];
            float s1 = 0.0f, s2 = 0.0f;
#pragma unroll
            for (int c = 0; c < C; c++) {
                float s = 0.0f;
#pragma unroll
                for (int k = 0; k < C; k++) s = fmaf(hv[k], W2s[k][h * C + c], s);
                o[c] = s;
                s1 = fmaf(s, As2[h * C + c], s1);
                s2 = fmaf(s, Ad2[h * C + c], s2);
            }
            g_aldst2[n * H + h] = s2;
            uint4 u;
            __half2* hp = (__half2*)&u;
            hp[0] = __floats2half2_rn(o[0], o[1]);
            hp[1] = __floats2half2_rn(o[2], o[3]);
            hp[2] = __floats2half2_rn(o[4], o[5]);
            hp[3] = __floats2half2_rn(o[6], s1);   // pack alsrc into pad slot
            *(uint4*)&g_xh2[(size_t)n * HCP + h * CP] = u;
        }
    } else {
        if (tid < 32) {
            const int nn = blockIdx.x * 32 + tid;
            if (nn < NN) {
                float v[C];
#pragma unroll
                for (int c = 0; c < C; c++) {
                    float s = 0.0f;
#pragma unroll
                    for (int hh = 0; hh < H; hh++) s += sm[tid][hh][c];
                    v[c] = s * (1.0f / H) + b[c];
                }
                float mx = v[0];
#pragma unroll
                for (int c = 1; c < C; c++) mx = fmaxf(mx, v[c]);
                float se = 0.0f;
#pragma unroll
                for (int c = 0; c < C; c++) se += __expf(v[c] - mx);
                const float lse = mx + logf(se);
#pragma unroll
                for (int c = 0; c < C; c++) out[nn * C + c] = v[c] - lse;
            }
        }
    }
}

extern "C" void kernel_launch(void* const* d_in, const int* in_sizes, int n_in,
                              void* d_out, int out_size) {
    const float* x      = (const float*)d_in[0];
    const int*   ei     = (const int*)  d_in[1];
    const float* W1     = (const float*)d_in[2];
    const float* a_src1 = (const float*)d_in[3];
    const float* a_dst1 = (const float*)d_in[4];
    const float* b1     = (const float*)d_in[5];
    const float* W2     = (const float*)d_in[6];
    const float* a_src2 = (const float*)d_in[7];
    const float* a_dst2 = (const float*)d_in[8];
    const float* b2     = (const float*)d_in[9];
    float* out = (float*)d_out;

    const int EB = (ET + 255) / 256;
    const int NB = (NN + 31) / 32;

    // ----- prep + bucket CSR -----
    k_prep   <<<(FIN * BN + 255) / 256, 256>>>(W1, a_src1, a_dst1);
    k_zero   <<<(NN + 255) / 256, 256>>>();
    k_scatter<<<EB, 256>>>(ei);

    // ----- layer 1 (+ fused layer-2 projection) -----
    k_gemm1  <<<(NN + 127) / 128, 256>>>(x);
    k_node<0><<<NB, 448>>>(b1, W2, a_src2, a_dst2, out);

    // ----- layer 2 -----
    k_node<1><<<NB, 448>>>(b2, W2, a_src2, a_dst2, out);
}